// round 15
// baseline (speedup 1.0000x reference)
#include <cuda_runtime.h>
#include <cuda_fp16.h>
#include <cstdint>
#include <cstddef>

// Problem dims (fixed by the dataset)
#define M_DIM   8192      // 4*2048 rows of x
#define IN_DIM  4096      // K of main GEMM
#define OUT_DIM 11008     // N of main GEMM
#define RANK_   192
#define KPACK   576       // 3 * RANK_  (compensated-product K concat)

// ---------------------------------------------------------------------------
// Scratch (static __device__ arrays — allocation-free per harness rules)
// ---------------------------------------------------------------------------
__device__ __align__(256) float  g_w  [(size_t)OUT_DIM * IN_DIM];  // weight+delta fp32
__device__ __align__(256) __half g_xh [(size_t)M_DIM  * IN_DIM];   // x as fp16
__device__ __align__(256) __half g_wh [(size_t)OUT_DIM * IN_DIM];  // quantized w fp16
__device__ __align__(256) __half g_bdp[(size_t)OUT_DIM * KPACK];   // [Ah|Ah|Al] of 64*Bd
__device__ __align__(256) __half g_bup[(size_t)IN_DIM * KPACK];    // [Bh|Bl|Bh] of 64*Bu, [N,K]

// ---------------------------------------------------------------------------
// x -> fp16
// ---------------------------------------------------------------------------
__global__ void cvt_half_kernel(const float* __restrict__ in,
                                __half* __restrict__ out, int n4) {
    int i = blockIdx.x * 256 + threadIdx.x;
    if (i < n4) {
        float4 v = reinterpret_cast<const float4*>(in)[i];
        __half2 h0 = __floats2half2_rn(v.x, v.y);
        __half2 h1 = __floats2half2_rn(v.z, v.w);
        uint2 p;
        p.x = *reinterpret_cast<uint32_t*>(&h0);
        p.y = *reinterpret_cast<uint32_t*>(&h1);
        reinterpret_cast<uint2*>(out)[i] = p;
    }
}

// ---------------------------------------------------------------------------
// Pack kernels: hi/lo fp16 split of 64*Bd / 64*Bu, K-concatenated so that a
// single fp16 GEMM computes Ah*Bh + Ah*Bl + Al*Bh (fp32-accurate product).
// ---------------------------------------------------------------------------
__global__ void pack_bd_kernel(const float* __restrict__ bd,
                               __half* __restrict__ out) {
    size_t i = (size_t)blockIdx.x * 256 + threadIdx.x;
    if (i < (size_t)OUT_DIM * KPACK) {
        int o = (int)(i / KPACK), c = (int)(i % KPACK);
        int r = (c < 192) ? c : ((c < 384) ? c - 192 : c - 384);
        float v = bd[(size_t)o * RANK_ + r] * 64.0f;
        __half h = __float2half_rn(v);
        out[i] = (c < 384) ? h : __float2half_rn(v - __half2float(h));
    }
}

// Tiled-transpose pack for Bu — coalesced reads AND writes.
__global__ void pack_bu_kernel(const float* __restrict__ bu,
                               __half* __restrict__ out) {
    __shared__ float t[32][33];
    const int r0 = blockIdx.x * 32;
    const int n0 = blockIdx.y * 32;
    const int tx = threadIdx.x, ty = threadIdx.y;   // 32 x 8

    #pragma unroll
    for (int j = 0; j < 32; j += 8)
        t[ty + j][tx] = bu[(size_t)(r0 + ty + j) * IN_DIM + n0 + tx];
    __syncthreads();

    #pragma unroll
    for (int j = 0; j < 32; j += 8) {
        const int n = n0 + ty + j;
        float v = t[tx][ty + j] * 64.0f;
        __half h = __float2half_rn(v);
        __half l = __float2half_rn(v - __half2float(h));
        __half* o = out + (size_t)n * KPACK + r0 + tx;
        o[0]   = h;
        o[192] = l;
        o[384] = h;
    }
}

// ---------------------------------------------------------------------------
// Row-wise 4-bit asymmetric fake quant: fp32 g_w (row cached) -> fp16 g_wh.
// ---------------------------------------------------------------------------
__global__ void quant_kernel(const float* __restrict__ w, __half* __restrict__ wh) {
    __shared__ float row[IN_DIM];
    __shared__ float smn[8], smx[8];
    __shared__ float s_scale, s_zero;

    const int rix = blockIdx.x;
    const float* p = w + (size_t)rix * IN_DIM;
    __half* po = wh + (size_t)rix * IN_DIM;
    const int tid = threadIdx.x;

    float mn = 0.0f, mx = 0.0f;
    #pragma unroll
    for (int i = tid; i < IN_DIM / 4; i += 256) {
        float4 v = reinterpret_cast<const float4*>(p)[i];
        reinterpret_cast<float4*>(row)[i] = v;
        mn = fminf(mn, fminf(fminf(v.x, v.y), fminf(v.z, v.w)));
        mx = fmaxf(mx, fmaxf(fmaxf(v.x, v.y), fmaxf(v.z, v.w)));
    }
    #pragma unroll
    for (int o = 16; o; o >>= 1) {
        mn = fminf(mn, __shfl_xor_sync(0xffffffffu, mn, o));
        mx = fmaxf(mx, __shfl_xor_sync(0xffffffffu, mx, o));
    }
    const int warp = tid >> 5, lane = tid & 31;
    if (lane == 0) { smn[warp] = mn; smx[warp] = mx; }
    __syncthreads();
    if (tid == 0) {
        float a = smn[0], b = smx[0];
        #pragma unroll
        for (int i = 1; i < 8; i++) { a = fminf(a, smn[i]); b = fmaxf(b, smx[i]); }
        float sc = fmaxf((b - a) / 15.0f, 1e-8f);
        s_scale = sc;
        s_zero  = rintf(-a / sc);
    }
    __syncthreads();
    const float sc = s_scale, z = s_zero;

    #pragma unroll
    for (int i = tid; i < IN_DIM / 4; i += 256) {
        float4 v = reinterpret_cast<float4*>(row)[i];
        float q0 = (fminf(fmaxf(rintf(v.x / sc) + z, 0.0f), 15.0f) - z) * sc;
        float q1 = (fminf(fmaxf(rintf(v.y / sc) + z, 0.0f), 15.0f) - z) * sc;
        float q2 = (fminf(fmaxf(rintf(v.z / sc) + z, 0.0f), 15.0f) - z) * sc;
        float q3 = (fminf(fmaxf(rintf(v.w / sc) + z, 0.0f), 15.0f) - z) * sc;
        __half2 h0 = __floats2half2_rn(q0, q1);
        __half2 h1 = __floats2half2_rn(q2, q3);
        uint2 pk;
        pk.x = *reinterpret_cast<uint32_t*>(&h0);
        pk.y = *reinterpret_cast<uint32_t*>(&h1);
        reinterpret_cast<uint2*>(po)[i] = pk;
    }
}

// ---------------------------------------------------------------------------
// Shared GEMM building blocks
// ---------------------------------------------------------------------------
__device__ __forceinline__ void cp16(uint32_t s, const void* g) {
    asm volatile("cp.async.cg.shared.global [%0], [%1], 16;\n" :: "r"(s), "l"(g));
}
__device__ __forceinline__ void ldsm_x4(uint32_t* r, uint32_t addr) {
    asm volatile("ldmatrix.sync.aligned.m8n8.x4.shared.b16 {%0,%1,%2,%3}, [%4];"
                 : "=r"(r[0]), "=r"(r[1]), "=r"(r[2]), "=r"(r[3]) : "r"(addr));
}
__device__ __forceinline__ void mma_f16(float* d, const uint32_t* a,
                                        uint32_t b0, uint32_t b1) {
    asm volatile(
        "mma.sync.aligned.m16n8k16.row.col.f32.f16.f16.f32 "
        "{%0,%1,%2,%3}, {%4,%5,%6,%7}, {%8,%9}, {%0,%1,%2,%3};\n"
        : "+f"(d[0]), "+f"(d[1]), "+f"(d[2]), "+f"(d[3])
        : "r"(a[0]), "r"(a[1]), "r"(a[2]), "r"(a[3]), "r"(b0), "r"(b1));
}

// Main GEMM geometry: CTA 128x128, 256 thr, 2 CTA/SM, BKH=64, 3-stage.
#define BM 128
#define BN 128
#define BKH 64
#define ROWB 144
#define A_BYTES (BM * ROWB)               // 18432
#define B_BYTES (BN * ROWB)               // 18432
#define STAGE_BYTES (A_BYTES + B_BYTES)   // 36864
#define NSTAGE 3
#define GEMM_SMEM (NSTAGE * STAGE_BYTES)  // 110592
#define KTILES_MAIN (IN_DIM / BKH)        // 64
#define MTILES (M_DIM / BM)               // 64
#define NTILES (OUT_DIM / BN)             // 86
#define TOTAL_TILES (MTILES * NTILES)     // 5504
#define NPERSIST 304                      // 2 CTAs/SM x 152 SMs (GB300)
#define EPI_STRIDE 136

// Delta GEMM geometry: 128x128 / 256 thr / 2 CTA/SM, BKH=32, 5-stage.
#define DBKH 32
#define DROWB 80
#define DA_BYTES (BM * DROWB)             // 10240
#define DB_BYTES (BN * DROWB)             // 10240
#define DSTAGE_BYTES (DA_BYTES + DB_BYTES)  // 20480
#define DNSTAGE 5
#define DGEMM_SMEM (DNSTAGE * DSTAGE_BYTES) // 102400
#define KTILES_DELTA (KPACK / DBKH)       // 18

// ---------------------------------------------------------------------------
// Delta GEMM (fp16, K=576): g_w[11008, 4096] = weight + (bdp @ bup^T)/4096
// ---------------------------------------------------------------------------
__global__ __launch_bounds__(256, 2)
void gemm_delta_f16(const __half* __restrict__ ap, const __half* __restrict__ bp,
                    const float* __restrict__ wgt, float* __restrict__ outw) {
    extern __shared__ __align__(128) unsigned char smem[];
    const uint32_t sb = (uint32_t)__cvta_generic_to_shared(smem);
    const int tid = threadIdx.x, warp = tid >> 5, lane = tid & 31;
    const int wm = warp & 1, wn = warp >> 1;

    const int mBase = blockIdx.y * BM, nBase = blockIdx.x * BN;

    const __half* gA[2]; uint32_t sAoff[2];
    const __half* gB[2]; uint32_t sBoff[2];
    #pragma unroll
    for (int i = 0; i < 2; i++) {
        int c = tid + i * 256;
        int r = c >> 2, s = c & 3;
        gA[i] = ap + (size_t)(mBase + r) * KPACK + s * 8;
        sAoff[i] = r * DROWB + s * 16;
        gB[i] = bp + (size_t)(nBase + r) * KPACK + s * 8;
        sBoff[i] = DA_BYTES + r * DROWB + s * 16;
    }

    auto issue = [&](int kt) {
        const uint32_t base = sb + (uint32_t)(kt % DNSTAGE) * DSTAGE_BYTES;
        const int koff = kt * DBKH;
        #pragma unroll
        for (int i = 0; i < 2; i++) cp16(base + sAoff[i], gA[i] + koff);
        #pragma unroll
        for (int i = 0; i < 2; i++) cp16(base + sBoff[i], gB[i] + koff);
        asm volatile("cp.async.commit_group;\n");
    };

    const int mat = lane >> 3, mrow = lane & 7;
    const uint32_t aAddr0 = (uint32_t)(wm * 64 + ((mat & 1) << 3) + mrow) * DROWB
                          + ((mat >> 1) << 4);
    const uint32_t bAddr0 = DA_BYTES
                          + (uint32_t)(wn * 32 + ((mat >> 1) << 3) + mrow) * DROWB
                          + ((mat & 1) << 4);

    float acc[4][4][4];
    #pragma unroll
    for (int i = 0; i < 4; i++)
        #pragma unroll
        for (int j = 0; j < 4; j++)
            #pragma unroll
            for (int k = 0; k < 4; k++) acc[i][j][k] = 0.0f;

    issue(0); issue(1); issue(2); issue(3);

    for (int kt = 0; kt < KTILES_DELTA; ++kt) {
        const int rem = KTILES_DELTA - 1 - kt;
        if (rem >= 3)      { asm volatile("cp.async.wait_group 3;\n"); }
        else if (rem == 2) { asm volatile("cp.async.wait_group 2;\n"); }
        else if (rem == 1) { asm volatile("cp.async.wait_group 1;\n"); }
        else               { asm volatile("cp.async.wait_group 0;\n"); }
        __syncthreads();
        if (kt + 4 < KTILES_DELTA) issue(kt + 4);

        const uint32_t base = sb + (uint32_t)(kt % DNSTAGE) * DSTAGE_BYTES;

        #pragma unroll
        for (int kk = 0; kk < 2; ++kk) {
            uint32_t af[4][4], bf[2][4];
            #pragma unroll
            for (int mi = 0; mi < 4; ++mi)
                ldsm_x4(af[mi], base + aAddr0 + mi * (16 * DROWB) + kk * 32);
            #pragma unroll
            for (int nj = 0; nj < 2; ++nj)
                ldsm_x4(bf[nj], base + bAddr0 + nj * (16 * DROWB) + kk * 32);
            #pragma unroll
            for (int mi = 0; mi < 4; ++mi) {
                #pragma unroll
                for (int nj = 0; nj < 2; ++nj) {
                    mma_f16(acc[mi][nj * 2],     af[mi], bf[nj][0], bf[nj][1]);
                    mma_f16(acc[mi][nj * 2 + 1], af[mi], bf[nj][2], bf[nj][3]);
                }
            }
        }
    }

    // Epilogue via smem staging, then coalesced float4 stream.
    __syncthreads();
    float* st = reinterpret_cast<float*>(smem);
    {
        const int mr = wm * 64 + (lane >> 2);
        const int nc = wn * 32 + ((lane & 3) << 1);
        #pragma unroll
        for (int mi = 0; mi < 4; ++mi) {
            const int m0 = mr + mi * 16;
            #pragma unroll
            for (int njh = 0; njh < 4; ++njh) {
                const int n = nc + njh * 8;
                st[m0 * EPI_STRIDE + n]           = acc[mi][njh][0];
                st[m0 * EPI_STRIDE + n + 1]       = acc[mi][njh][1];
                st[(m0 + 8) * EPI_STRIDE + n]     = acc[mi][njh][2];
                st[(m0 + 8) * EPI_STRIDE + n + 1] = acc[mi][njh][3];
            }
        }
    }
    __syncthreads();
    const float SC = 1.0f / 4096.0f;
    #pragma unroll
    for (int it = 0; it < 16; ++it) {
        int i = tid + it * 256;
        int row = i >> 5, c4 = i & 31;
        float4 v = *reinterpret_cast<float4*>(&st[row * EPI_STRIDE + c4 * 4]);
        size_t gofs = (size_t)(mBase + row) * IN_DIM + nBase + c4 * 4;
        float4 w4 = *reinterpret_cast<const float4*>(&wgt[gofs]);
        v.x = v.x * SC + w4.x;
        v.y = v.y * SC + w4.y;
        v.z = v.z * SC + w4.z;
        v.w = v.w * SC + w4.w;
        *reinterpret_cast<float4*>(&outw[gofs]) = v;
    }
}

// ---------------------------------------------------------------------------
// Main GEMM (R15: PERSISTENT): out[8192,11008] = xh @ wh^T + bias
// 304 persistent CTAs; cp.async pipeline runs continuously across tiles —
// epilogue of tile t overlaps the prefetch/compute of tile t+1.
// ---------------------------------------------------------------------------
__global__ __launch_bounds__(256, 2)
void gemm_main_fp16(const __half* __restrict__ xh, const __half* __restrict__ wh,
                    const float* __restrict__ bias, float* __restrict__ out) {
    extern __shared__ __align__(128) unsigned char smem[];
    const uint32_t sb = (uint32_t)__cvta_generic_to_shared(smem);
    const int tid = threadIdx.x, warp = tid >> 5, lane = tid & 31;
    const int wm = warp & 1, wn = warp >> 1;   // 2M x 4N warps, warp tile 64x32
    const int bid = blockIdx.x;

    const int ntiles = (TOTAL_TILES - bid + NPERSIST - 1) / NPERSIST;
    const int C = ntiles * KTILES_MAIN;        // total k-chunks for this CTA

    // Per-thread cp.async constants: rows r0+32i (i<4), col chunk s0.
    const int r0 = tid >> 3, s0 = tid & 7;
    const uint32_t sA0 = (uint32_t)(r0 * ROWB + s0 * 16);
    const uint32_t sB0 = (uint32_t)(A_BYTES + r0 * ROWB + s0 * 16);

    // Decode swizzled tile -> (mBase, nBase).
    auto decode = [&](int tile, int& mB, int& nB) {
        if (tile < MTILES * 80) {
            int sc = tile >> 9, loc = tile & 511;
            nB = (sc * 8 + (loc & 7)) * BN;
            mB = (loc >> 3) * BM;
        } else {
            int loc = tile - MTILES * 80;
            nB = (80 + loc % 6) * BN;
            mB = (loc / 6) * BM;
        }
    };

    // Issue all 8 cp.async chunks for global chunk index c into stage st.
    auto issue = [&](int c, int st) {
        const int kt = c & (KTILES_MAIN - 1);
        const int tile = bid + (c >> 6) * NPERSIST;
        int mB, nB;
        decode(tile, mB, nB);
        const uint32_t base = sb + (uint32_t)st * STAGE_BYTES;
        const size_t aOfs = (size_t)(mB + r0) * IN_DIM + s0 * 8 + kt * BKH;
        const size_t bOfs = (size_t)(nB + r0) * IN_DIM + s0 * 8 + kt * BKH;
        #pragma unroll
        for (int i = 0; i < 4; i++)
            cp16(base + sA0 + i * (32 * ROWB), xh + aOfs + (size_t)i * 32 * IN_DIM);
        #pragma unroll
        for (int i = 0; i < 4; i++)
            cp16(base + sB0 + i * (32 * ROWB), wh + bOfs + (size_t)i * 32 * IN_DIM);
        asm volatile("cp.async.commit_group;\n");
    };

    const int mat = lane >> 3, mrow = lane & 7;
    const uint32_t aAddr0 = (uint32_t)(wm * 64 + ((mat & 1) << 3) + mrow) * ROWB
                          + ((mat >> 1) << 4);
    const uint32_t bAddr0 = A_BYTES
                          + (uint32_t)(wn * 32 + ((mat >> 1) << 3) + mrow) * ROWB
                          + ((mat & 1) << 4);

    float acc[4][4][4];
    #pragma unroll
    for (int i = 0; i < 4; i++)
        #pragma unroll
        for (int j = 0; j < 4; j++)
            #pragma unroll
            for (int k = 0; k < 4; k++) acc[i][j][k] = 0.0f;

    issue(0, 0); issue(1, 1);

    int stC = 0, stI = 2;   // stage of current chunk / of chunk c+2
    for (int c = 0; c < C; ++c) {
        if (c < C - 1) { asm volatile("cp.async.wait_group 1;\n"); }
        else           { asm volatile("cp.async.wait_group 0;\n"); }
        __syncthreads();
        if (c + 2 < C) issue(c + 2, stI);

        const uint32_t base = sb + (uint32_t)stC * STAGE_BYTES;

        #pragma unroll
        for (int kk = 0; kk < 4; ++kk) {
            uint32_t af[4][4], bf[2][4];
            #pragma unroll
            for (int mi = 0; mi < 4; ++mi)
                ldsm_x4(af[mi], base + aAddr0 + mi * (16 * ROWB) + kk * 32);
            #pragma unroll
            for (int nj = 0; nj < 2; ++nj)
                ldsm_x4(bf[nj], base + bAddr0 + nj * (16 * ROWB) + kk * 32);
            #pragma unroll
            for (int mi = 0; mi < 4; ++mi) {
                #pragma unroll
                for (int nj = 0; nj < 2; ++nj) {
                    mma_f16(acc[mi][nj * 2],     af[mi], bf[nj][0], bf[nj][1]);
                    mma_f16(acc[mi][nj * 2 + 1], af[mi], bf[nj][2], bf[nj][3]);
                }
            }
        }

        if ((c & (KTILES_MAIN - 1)) == KTILES_MAIN - 1) {
            // Epilogue for the finished tile — overlaps next tile's prefetch.
            const int tile = bid + (c >> 6) * NPERSIST;
            int mB, nB;
            decode(tile, mB, nB);
            const int mRow = mB + wm * 64 + (lane >> 2);
            const int nCol = nB + wn * 32 + ((lane & 3) << 1);
            #pragma unroll
            for (int mi = 0; mi < 4; ++mi) {
                const int m0 = mRow + mi * 16;
                #pragma unroll
                for (int njh = 0; njh < 4; ++njh) {
                    const int n = nCol + njh * 8;
                    float2 b2 = *reinterpret_cast<const float2*>(&bias[n]);
                    float2 o0 = make_float2(acc[mi][njh][0] + b2.x,
                                            acc[mi][njh][1] + b2.y);
                    float2 o1 = make_float2(acc[mi][njh][2] + b2.x,
                                            acc[mi][njh][3] + b2.y);
                    *reinterpret_cast<float2*>(&out[(size_t)m0 * OUT_DIM + n]) = o0;
                    *reinterpret_cast<float2*>(&out[(size_t)(m0 + 8) * OUT_DIM + n]) = o1;
                    acc[mi][njh][0] = 0.0f; acc[mi][njh][1] = 0.0f;
                    acc[mi][njh][2] = 0.0f; acc[mi][njh][3] = 0.0f;
                }
            }
        }

        stC = (stC == 2) ? 0 : stC + 1;
        stI = (stI == 2) ? 0 : stI + 1;
    }
}

// ---------------------------------------------------------------------------
// Launch — pack_bd + cvt_half forked onto a side stream:
//   side: pack_bd -> ev_pack -> cvt_half -> ev_join
//   main: pack_bu -> wait(ev_pack) -> delta -> quant -> wait(ev_join) -> main
// ---------------------------------------------------------------------------
extern "C" void kernel_launch(void* const* d_in, const int* in_sizes, int n_in,
                              void* d_out, int out_size) {
    const float *x = nullptr, *weight = nullptr, *Bd = nullptr,
                *Bu = nullptr, *bias = nullptr;
    for (int i = 0; i < n_in; i++) {
        switch (in_sizes[i]) {
            case 33554432: x      = (const float*)d_in[i]; break;  // 8192*4096
            case 45088768: weight = (const float*)d_in[i]; break;  // 11008*4096
            case 2113536:  Bd     = (const float*)d_in[i]; break;  // 11008*192
            case 786432:   Bu     = (const float*)d_in[i]; break;  // 192*4096
            case 11008:    bias   = (const float*)d_in[i]; break;
        }
    }
    if (!x && n_in > 0)      x      = (const float*)d_in[0];
    if (!weight && n_in > 1) weight = (const float*)d_in[1];
    if (!Bd && n_in > 2)     Bd     = (const float*)d_in[2];
    if (!Bu && n_in > 3)     Bu     = (const float*)d_in[3];
    if (!bias && n_in > 4)   bias   = (const float*)d_in[4];

    float *gw;
    __half *gxh, *gwh, *gbdp, *gbup;
    cudaGetSymbolAddress((void**)&gw,   g_w);
    cudaGetSymbolAddress((void**)&gxh,  g_xh);
    cudaGetSymbolAddress((void**)&gwh,  g_wh);
    cudaGetSymbolAddress((void**)&gbdp, g_bdp);
    cudaGetSymbolAddress((void**)&gbup, g_bup);

    cudaFuncSetAttribute(gemm_delta_f16,
                         cudaFuncAttributeMaxDynamicSharedMemorySize, DGEMM_SMEM);
    cudaFuncSetAttribute(gemm_main_fp16,
                         cudaFuncAttributeMaxDynamicSharedMemorySize, GEMM_SMEM);

    // One-time host resources (no device memory involved).
    static cudaStream_t s_side = nullptr;
    static cudaEvent_t ev_fork = nullptr, ev_pack = nullptr, ev_join = nullptr;
    if (s_side == nullptr) {
        cudaStreamCreateWithFlags(&s_side, cudaStreamNonBlocking);
        cudaEventCreateWithFlags(&ev_fork, cudaEventDisableTiming);
        cudaEventCreateWithFlags(&ev_pack, cudaEventDisableTiming);
        cudaEventCreateWithFlags(&ev_join, cudaEventDisableTiming);
    }

    // Fork side stream: pack_bd (feeds delta), then cvt_half (feeds main GEMM).
    cudaEventRecord(ev_fork, 0);
    cudaStreamWaitEvent(s_side, ev_fork, 0);
    pack_bd_kernel<<<((size_t)OUT_DIM * KPACK + 255) / 256, 256, 0, s_side>>>(
        Bd, gbdp);
    cudaEventRecord(ev_pack, s_side);
    cvt_half_kernel<<<(33554432 / 4 + 255) / 256, 256, 0, s_side>>>(
        x, gxh, 33554432 / 4);
    cudaEventRecord(ev_join, s_side);

    // Main-stream chain: pack_bu || pack_bd, then delta -> quant.
    pack_bu_kernel<<<dim3(RANK_ / 32, IN_DIM / 32), dim3(32, 8)>>>(Bu, gbup);
    cudaStreamWaitEvent(0, ev_pack, 0);
    gemm_delta_f16<<<dim3(IN_DIM / BN, OUT_DIM / BM), 256, DGEMM_SMEM>>>(
        gbdp, gbup, weight, gw);
    quant_kernel<<<OUT_DIM, 256>>>(gw, gwh);

    // Join: main GEMM needs g_xh.
    cudaStreamWaitEvent(0, ev_join, 0);
    gemm_main_fp16<<<NPERSIST, 256, GEMM_SMEM>>>(gxh, gwh, bias, (float*)d_out);
}

// round 16
// speedup vs baseline: 1.0674x; 1.0674x over previous
#include <cuda_runtime.h>
#include <cuda_fp16.h>
#include <cstdint>
#include <cstddef>

// Problem dims (fixed by the dataset)
#define M_DIM   8192      // 4*2048 rows of x
#define IN_DIM  4096      // K of main GEMM
#define OUT_DIM 11008     // N of main GEMM
#define RANK_   192
#define KPACK   576       // 3 * RANK_  (compensated-product K concat)

// ---------------------------------------------------------------------------
// Scratch (static __device__ arrays — allocation-free per harness rules)
// ---------------------------------------------------------------------------
__device__ __align__(256) float  g_w  [(size_t)OUT_DIM * IN_DIM];  // weight+delta fp32
__device__ __align__(256) __half g_xh [(size_t)M_DIM  * IN_DIM];   // x as fp16
__device__ __align__(256) __half g_wh [(size_t)OUT_DIM * IN_DIM];  // quantized w fp16
__device__ __align__(256) __half g_bdp[(size_t)OUT_DIM * KPACK];   // [Ah|Ah|Al] of 64*Bd
__device__ __align__(256) __half g_bup[(size_t)IN_DIM * KPACK];    // [Bh|Bl|Bh] of 64*Bu, [N,K]

// ---------------------------------------------------------------------------
// x -> fp16
// ---------------------------------------------------------------------------
__global__ void cvt_half_kernel(const float* __restrict__ in,
                                __half* __restrict__ out, int n4) {
    int i = blockIdx.x * 256 + threadIdx.x;
    if (i < n4) {
        float4 v = reinterpret_cast<const float4*>(in)[i];
        __half2 h0 = __floats2half2_rn(v.x, v.y);
        __half2 h1 = __floats2half2_rn(v.z, v.w);
        uint2 p;
        p.x = *reinterpret_cast<uint32_t*>(&h0);
        p.y = *reinterpret_cast<uint32_t*>(&h1);
        reinterpret_cast<uint2*>(out)[i] = p;
    }
}

// ---------------------------------------------------------------------------
// Pack kernels: hi/lo fp16 split of 64*Bd / 64*Bu, K-concatenated so that a
// single fp16 GEMM computes Ah*Bh + Ah*Bl + Al*Bh (fp32-accurate product).
// ---------------------------------------------------------------------------
__global__ void pack_bd_kernel(const float* __restrict__ bd,
                               __half* __restrict__ out) {
    size_t i = (size_t)blockIdx.x * 256 + threadIdx.x;
    if (i < (size_t)OUT_DIM * KPACK) {
        int o = (int)(i / KPACK), c = (int)(i % KPACK);
        int r = (c < 192) ? c : ((c < 384) ? c - 192 : c - 384);
        float v = bd[(size_t)o * RANK_ + r] * 64.0f;
        __half h = __float2half_rn(v);
        out[i] = (c < 384) ? h : __float2half_rn(v - __half2float(h));
    }
}

// Tiled-transpose pack for Bu — coalesced reads AND writes.
__global__ void pack_bu_kernel(const float* __restrict__ bu,
                               __half* __restrict__ out) {
    __shared__ float t[32][33];
    const int r0 = blockIdx.x * 32;
    const int n0 = blockIdx.y * 32;
    const int tx = threadIdx.x, ty = threadIdx.y;   // 32 x 8

    #pragma unroll
    for (int j = 0; j < 32; j += 8)
        t[ty + j][tx] = bu[(size_t)(r0 + ty + j) * IN_DIM + n0 + tx];
    __syncthreads();

    #pragma unroll
    for (int j = 0; j < 32; j += 8) {
        const int n = n0 + ty + j;
        float v = t[tx][ty + j] * 64.0f;
        __half h = __float2half_rn(v);
        __half l = __float2half_rn(v - __half2float(h));
        __half* o = out + (size_t)n * KPACK + r0 + tx;
        o[0]   = h;
        o[192] = l;
        o[384] = h;
    }
}

// ---------------------------------------------------------------------------
// Row-wise 4-bit asymmetric fake quant: fp32 g_w (row cached) -> fp16 g_wh.
// rowOff selects the half being processed.
// ---------------------------------------------------------------------------
__global__ void quant_kernel(const float* __restrict__ w, __half* __restrict__ wh,
                             int rowOff) {
    __shared__ float row[IN_DIM];
    __shared__ float smn[8], smx[8];
    __shared__ float s_scale, s_zero;

    const int rix = blockIdx.x + rowOff;
    const float* p = w + (size_t)rix * IN_DIM;
    __half* po = wh + (size_t)rix * IN_DIM;
    const int tid = threadIdx.x;

    float mn = 0.0f, mx = 0.0f;
    #pragma unroll
    for (int i = tid; i < IN_DIM / 4; i += 256) {
        float4 v = reinterpret_cast<const float4*>(p)[i];
        reinterpret_cast<float4*>(row)[i] = v;
        mn = fminf(mn, fminf(fminf(v.x, v.y), fminf(v.z, v.w)));
        mx = fmaxf(mx, fmaxf(fmaxf(v.x, v.y), fmaxf(v.z, v.w)));
    }
    #pragma unroll
    for (int o = 16; o; o >>= 1) {
        mn = fminf(mn, __shfl_xor_sync(0xffffffffu, mn, o));
        mx = fmaxf(mx, __shfl_xor_sync(0xffffffffu, mx, o));
    }
    const int warp = tid >> 5, lane = tid & 31;
    if (lane == 0) { smn[warp] = mn; smx[warp] = mx; }
    __syncthreads();
    if (tid == 0) {
        float a = smn[0], b = smx[0];
        #pragma unroll
        for (int i = 1; i < 8; i++) { a = fminf(a, smn[i]); b = fmaxf(b, smx[i]); }
        float sc = fmaxf((b - a) / 15.0f, 1e-8f);
        s_scale = sc;
        s_zero  = rintf(-a / sc);
    }
    __syncthreads();
    const float sc = s_scale, z = s_zero;

    #pragma unroll
    for (int i = tid; i < IN_DIM / 4; i += 256) {
        float4 v = reinterpret_cast<float4*>(row)[i];
        float q0 = (fminf(fmaxf(rintf(v.x / sc) + z, 0.0f), 15.0f) - z) * sc;
        float q1 = (fminf(fmaxf(rintf(v.y / sc) + z, 0.0f), 15.0f) - z) * sc;
        float q2 = (fminf(fmaxf(rintf(v.z / sc) + z, 0.0f), 15.0f) - z) * sc;
        float q3 = (fminf(fmaxf(rintf(v.w / sc) + z, 0.0f), 15.0f) - z) * sc;
        __half2 h0 = __floats2half2_rn(q0, q1);
        __half2 h1 = __floats2half2_rn(q2, q3);
        uint2 pk;
        pk.x = *reinterpret_cast<uint32_t*>(&h0);
        pk.y = *reinterpret_cast<uint32_t*>(&h1);
        reinterpret_cast<uint2*>(po)[i] = pk;
    }
}

// ---------------------------------------------------------------------------
// Shared GEMM building blocks
// ---------------------------------------------------------------------------
__device__ __forceinline__ void cp16(uint32_t s, const void* g) {
    asm volatile("cp.async.cg.shared.global [%0], [%1], 16;\n" :: "r"(s), "l"(g));
}
__device__ __forceinline__ void ldsm_x4(uint32_t* r, uint32_t addr) {
    asm volatile("ldmatrix.sync.aligned.m8n8.x4.shared.b16 {%0,%1,%2,%3}, [%4];"
                 : "=r"(r[0]), "=r"(r[1]), "=r"(r[2]), "=r"(r[3]) : "r"(addr));
}
__device__ __forceinline__ void mma_f16(float* d, const uint32_t* a,
                                        uint32_t b0, uint32_t b1) {
    asm volatile(
        "mma.sync.aligned.m16n8k16.row.col.f32.f16.f16.f32 "
        "{%0,%1,%2,%3}, {%4,%5,%6,%7}, {%8,%9}, {%0,%1,%2,%3};\n"
        : "+f"(d[0]), "+f"(d[1]), "+f"(d[2]), "+f"(d[3])
        : "r"(a[0]), "r"(a[1]), "r"(a[2]), "r"(a[3]), "r"(b0), "r"(b1));
}

// Main GEMM geometry (R9/R11/R14 optimum): CTA 128x128, 256 thr, 2 CTA/SM,
// K-chunk 64 halves, ROWB=144, 3-stage cp.async.
#define BM 128
#define BN 128
#define BKH 64
#define ROWB 144
#define A_BYTES (BM * ROWB)               // 18432
#define B_BYTES (BN * ROWB)               // 18432
#define STAGE_BYTES (A_BYTES + B_BYTES)   // 36864
#define NSTAGE 3
#define GEMM_SMEM (NSTAGE * STAGE_BYTES)  // 110592
#define KTILES_MAIN (IN_DIM / BKH)        // 64
#define MTILES (M_DIM / BM)               // 64
#define NT_HALF 43                        // n-tiles per half (86 total)
#define EPI_STRIDE 136

// Delta GEMM geometry: 128x128 / 256 thr / 2 CTA/SM, BKH=32, 5-stage.
#define DBKH 32
#define DROWB 80
#define DA_BYTES (BM * DROWB)             // 10240
#define DB_BYTES (BN * DROWB)             // 10240
#define DSTAGE_BYTES (DA_BYTES + DB_BYTES)  // 20480
#define DNSTAGE 5
#define DGEMM_SMEM (DNSTAGE * DSTAGE_BYTES) // 102400
#define KTILES_DELTA (KPACK / DBKH)       // 18

// ---------------------------------------------------------------------------
// Delta GEMM (fp16, K=576): g_w[11008, 4096] = weight + (bdp @ bup^T)/4096
// yOff selects the M-tile half.
// ---------------------------------------------------------------------------
__global__ __launch_bounds__(256, 2)
void gemm_delta_f16(const __half* __restrict__ ap, const __half* __restrict__ bp,
                    const float* __restrict__ wgt, float* __restrict__ outw,
                    int yOff) {
    extern __shared__ __align__(128) unsigned char smem[];
    const uint32_t sb = (uint32_t)__cvta_generic_to_shared(smem);
    const int tid = threadIdx.x, warp = tid >> 5, lane = tid & 31;
    const int wm = warp & 1, wn = warp >> 1;

    const int mBase = (blockIdx.y + yOff) * BM, nBase = blockIdx.x * BN;

    const __half* gA[2]; uint32_t sAoff[2];
    const __half* gB[2]; uint32_t sBoff[2];
    #pragma unroll
    for (int i = 0; i < 2; i++) {
        int c = tid + i * 256;
        int r = c >> 2, s = c & 3;
        gA[i] = ap + (size_t)(mBase + r) * KPACK + s * 8;
        sAoff[i] = r * DROWB + s * 16;
        gB[i] = bp + (size_t)(nBase + r) * KPACK + s * 8;
        sBoff[i] = DA_BYTES + r * DROWB + s * 16;
    }

    auto issue = [&](int kt) {
        const uint32_t base = sb + (uint32_t)(kt % DNSTAGE) * DSTAGE_BYTES;
        const int koff = kt * DBKH;
        #pragma unroll
        for (int i = 0; i < 2; i++) cp16(base + sAoff[i], gA[i] + koff);
        #pragma unroll
        for (int i = 0; i < 2; i++) cp16(base + sBoff[i], gB[i] + koff);
        asm volatile("cp.async.commit_group;\n");
    };

    const int mat = lane >> 3, mrow = lane & 7;
    const uint32_t aAddr0 = (uint32_t)(wm * 64 + ((mat & 1) << 3) + mrow) * DROWB
                          + ((mat >> 1) << 4);
    const uint32_t bAddr0 = DA_BYTES
                          + (uint32_t)(wn * 32 + ((mat >> 1) << 3) + mrow) * DROWB
                          + ((mat & 1) << 4);

    float acc[4][4][4];
    #pragma unroll
    for (int i = 0; i < 4; i++)
        #pragma unroll
        for (int j = 0; j < 4; j++)
            #pragma unroll
            for (int k = 0; k < 4; k++) acc[i][j][k] = 0.0f;

    issue(0); issue(1); issue(2); issue(3);

    for (int kt = 0; kt < KTILES_DELTA; ++kt) {
        const int rem = KTILES_DELTA - 1 - kt;
        if (rem >= 3)      { asm volatile("cp.async.wait_group 3;\n"); }
        else if (rem == 2) { asm volatile("cp.async.wait_group 2;\n"); }
        else if (rem == 1) { asm volatile("cp.async.wait_group 1;\n"); }
        else               { asm volatile("cp.async.wait_group 0;\n"); }
        __syncthreads();
        if (kt + 4 < KTILES_DELTA) issue(kt + 4);

        const uint32_t base = sb + (uint32_t)(kt % DNSTAGE) * DSTAGE_BYTES;

        #pragma unroll
        for (int kk = 0; kk < 2; ++kk) {
            uint32_t af[4][4], bf[2][4];
            #pragma unroll
            for (int mi = 0; mi < 4; ++mi)
                ldsm_x4(af[mi], base + aAddr0 + mi * (16 * DROWB) + kk * 32);
            #pragma unroll
            for (int nj = 0; nj < 2; ++nj)
                ldsm_x4(bf[nj], base + bAddr0 + nj * (16 * DROWB) + kk * 32);
            #pragma unroll
            for (int mi = 0; mi < 4; ++mi) {
                #pragma unroll
                for (int nj = 0; nj < 2; ++nj) {
                    mma_f16(acc[mi][nj * 2],     af[mi], bf[nj][0], bf[nj][1]);
                    mma_f16(acc[mi][nj * 2 + 1], af[mi], bf[nj][2], bf[nj][3]);
                }
            }
        }
    }

    // Epilogue via smem staging, then coalesced float4 stream.
    __syncthreads();
    float* st = reinterpret_cast<float*>(smem);
    {
        const int mr = wm * 64 + (lane >> 2);
        const int nc = wn * 32 + ((lane & 3) << 1);
        #pragma unroll
        for (int mi = 0; mi < 4; ++mi) {
            const int m0 = mr + mi * 16;
            #pragma unroll
            for (int njh = 0; njh < 4; ++njh) {
                const int n = nc + njh * 8;
                st[m0 * EPI_STRIDE + n]           = acc[mi][njh][0];
                st[m0 * EPI_STRIDE + n + 1]       = acc[mi][njh][1];
                st[(m0 + 8) * EPI_STRIDE + n]     = acc[mi][njh][2];
                st[(m0 + 8) * EPI_STRIDE + n + 1] = acc[mi][njh][3];
            }
        }
    }
    __syncthreads();
    const float SC = 1.0f / 4096.0f;
    #pragma unroll
    for (int it = 0; it < 16; ++it) {
        int i = tid + it * 256;
        int row = i >> 5, c4 = i & 31;
        float4 v = *reinterpret_cast<float4*>(&st[row * EPI_STRIDE + c4 * 4]);
        size_t gofs = (size_t)(mBase + row) * IN_DIM + nBase + c4 * 4;
        float4 w4 = *reinterpret_cast<const float4*>(&wgt[gofs]);
        v.x = v.x * SC + w4.x;
        v.y = v.y * SC + w4.y;
        v.z = v.z * SC + w4.z;
        v.w = v.w * SC + w4.w;
        *reinterpret_cast<float4*>(&outw[gofs]) = v;
    }
}

// ---------------------------------------------------------------------------
// Main GEMM half: out[:, nTileOff*128 .. +43*128) = xh @ wh^T + bias
// (R14 config; nTileOff selects the N half; 43-tile supercolumn swizzle)
// ---------------------------------------------------------------------------
__global__ __launch_bounds__(256, 2)
void gemm_main_fp16(const __half* __restrict__ xh, const __half* __restrict__ wh,
                    const float* __restrict__ bias, float* __restrict__ out,
                    int nTileOff) {
    extern __shared__ __align__(128) unsigned char smem[];
    const uint32_t sb = (uint32_t)__cvta_generic_to_shared(smem);
    const int tid = threadIdx.x, warp = tid >> 5, lane = tid & 31;
    const int wm = warp & 1, wn = warp >> 1;   // 2M x 4N warps, warp tile 64x32

    // 43-tile swizzle: 5 supercolumns of 8 + remainder 3.
    int g = blockIdx.x, mTile, nT;
    if (g < MTILES * 40) { int sc = g >> 9, loc = g & 511; nT = sc * 8 + (loc & 7); mTile = loc >> 3; }
    else                 { int loc = g - MTILES * 40; nT = 40 + loc % 3; mTile = loc / 3; }
    const int mBase = mTile * BM, nBase = (nTileOff + nT) * BN;

    const __half* gA[4]; uint32_t sAoff[4];
    const __half* gB[4]; uint32_t sBoff[4];
    #pragma unroll
    for (int i = 0; i < 4; i++) {
        int c = tid + i * 256;
        int r = c >> 3, s = c & 7;
        gA[i] = xh + (size_t)(mBase + r) * IN_DIM + s * 8;
        sAoff[i] = r * ROWB + s * 16;
        gB[i] = wh + (size_t)(nBase + r) * IN_DIM + s * 8;
        sBoff[i] = A_BYTES + r * ROWB + s * 16;
    }

    auto issue = [&](int kt) {
        const uint32_t base = sb + (uint32_t)(kt % NSTAGE) * STAGE_BYTES;
        const int koff = kt * BKH;
        #pragma unroll
        for (int i = 0; i < 4; i++) cp16(base + sAoff[i], gA[i] + koff);
        #pragma unroll
        for (int i = 0; i < 4; i++) cp16(base + sBoff[i], gB[i] + koff);
        asm volatile("cp.async.commit_group;\n");
    };

    const int mat = lane >> 3, mrow = lane & 7;
    const uint32_t aAddr0 = (uint32_t)(wm * 64 + ((mat & 1) << 3) + mrow) * ROWB
                          + ((mat >> 1) << 4);
    const uint32_t bAddr0 = A_BYTES
                          + (uint32_t)(wn * 32 + ((mat >> 1) << 3) + mrow) * ROWB
                          + ((mat & 1) << 4);

    float acc[4][4][4];
    #pragma unroll
    for (int i = 0; i < 4; i++)
        #pragma unroll
        for (int j = 0; j < 4; j++)
            #pragma unroll
            for (int k = 0; k < 4; k++) acc[i][j][k] = 0.0f;

    issue(0); issue(1);

    for (int kt = 0; kt < KTILES_MAIN; ++kt) {
        if (kt < KTILES_MAIN - 1) { asm volatile("cp.async.wait_group 1;\n"); }
        else                      { asm volatile("cp.async.wait_group 0;\n"); }
        __syncthreads();
        if (kt + 2 < KTILES_MAIN) issue(kt + 2);

        const uint32_t base = sb + (uint32_t)(kt % NSTAGE) * STAGE_BYTES;

        #pragma unroll
        for (int kk = 0; kk < 4; ++kk) {
            uint32_t af[4][4], bf[2][4];
            #pragma unroll
            for (int mi = 0; mi < 4; ++mi)
                ldsm_x4(af[mi], base + aAddr0 + mi * (16 * ROWB) + kk * 32);
            #pragma unroll
            for (int nj = 0; nj < 2; ++nj)
                ldsm_x4(bf[nj], base + bAddr0 + nj * (16 * ROWB) + kk * 32);
            #pragma unroll
            for (int mi = 0; mi < 4; ++mi) {
                #pragma unroll
                for (int nj = 0; nj < 2; ++nj) {
                    mma_f16(acc[mi][nj * 2],     af[mi], bf[nj][0], bf[nj][1]);
                    mma_f16(acc[mi][nj * 2 + 1], af[mi], bf[nj][2], bf[nj][3]);
                }
            }
        }
    }

    const int mRow = mBase + wm * 64 + (lane >> 2);
    const int nCol = nBase + wn * 32 + ((lane & 3) << 1);
    #pragma unroll
    for (int mi = 0; mi < 4; ++mi) {
        const int m0 = mRow + mi * 16;
        #pragma unroll
        for (int njh = 0; njh < 4; ++njh) {
            const int n = nCol + njh * 8;
            float2 b2 = *reinterpret_cast<const float2*>(&bias[n]);
            float2 o0 = make_float2(acc[mi][njh][0] + b2.x, acc[mi][njh][1] + b2.y);
            float2 o1 = make_float2(acc[mi][njh][2] + b2.x, acc[mi][njh][3] + b2.y);
            *reinterpret_cast<float2*>(&out[(size_t)m0 * OUT_DIM + n])       = o0;
            *reinterpret_cast<float2*>(&out[(size_t)(m0 + 8) * OUT_DIM + n]) = o1;
        }
    }
}

// ---------------------------------------------------------------------------
// Launch — half-split software pipeline across two streams:
//   side: pack_bd, cvt_half, [dA] quantA, [dB] quantB, mainB, ev_end
//   main: pack_bu, deltaA, deltaB, [qA] mainA, wait ev_end
// quant halves hide under deltaB / mainA; mainB backfills mainA's drain.
// ---------------------------------------------------------------------------
extern "C" void kernel_launch(void* const* d_in, const int* in_sizes, int n_in,
                              void* d_out, int out_size) {
    const float *x = nullptr, *weight = nullptr, *Bd = nullptr,
                *Bu = nullptr, *bias = nullptr;
    for (int i = 0; i < n_in; i++) {
        switch (in_sizes[i]) {
            case 33554432: x      = (const float*)d_in[i]; break;  // 8192*4096
            case 45088768: weight = (const float*)d_in[i]; break;  // 11008*4096
            case 2113536:  Bd     = (const float*)d_in[i]; break;  // 11008*192
            case 786432:   Bu     = (const float*)d_in[i]; break;  // 192*4096
            case 11008:    bias   = (const float*)d_in[i]; break;
        }
    }
    if (!x && n_in > 0)      x      = (const float*)d_in[0];
    if (!weight && n_in > 1) weight = (const float*)d_in[1];
    if (!Bd && n_in > 2)     Bd     = (const float*)d_in[2];
    if (!Bu && n_in > 3)     Bu     = (const float*)d_in[3];
    if (!bias && n_in > 4)   bias   = (const float*)d_in[4];

    float *gw;
    __half *gxh, *gwh, *gbdp, *gbup;
    cudaGetSymbolAddress((void**)&gw,   g_w);
    cudaGetSymbolAddress((void**)&gxh,  g_xh);
    cudaGetSymbolAddress((void**)&gwh,  g_wh);
    cudaGetSymbolAddress((void**)&gbdp, g_bdp);
    cudaGetSymbolAddress((void**)&gbup, g_bup);

    cudaFuncSetAttribute(gemm_delta_f16,
                         cudaFuncAttributeMaxDynamicSharedMemorySize, DGEMM_SMEM);
    cudaFuncSetAttribute(gemm_main_fp16,
                         cudaFuncAttributeMaxDynamicSharedMemorySize, GEMM_SMEM);

    // One-time host resources (no device memory involved).
    static cudaStream_t s_side = nullptr;
    static cudaEvent_t ev_fork = nullptr, ev_pack = nullptr;
    static cudaEvent_t ev_dA = nullptr, ev_dB = nullptr, ev_qA = nullptr,
                       ev_end = nullptr;
    if (s_side == nullptr) {
        cudaStreamCreateWithFlags(&s_side, cudaStreamNonBlocking);
        cudaEventCreateWithFlags(&ev_fork, cudaEventDisableTiming);
        cudaEventCreateWithFlags(&ev_pack, cudaEventDisableTiming);
        cudaEventCreateWithFlags(&ev_dA,   cudaEventDisableTiming);
        cudaEventCreateWithFlags(&ev_dB,   cudaEventDisableTiming);
        cudaEventCreateWithFlags(&ev_qA,   cudaEventDisableTiming);
        cudaEventCreateWithFlags(&ev_end,  cudaEventDisableTiming);
    }

    const int HROWS = OUT_DIM / 2;   // 5504

    // Fork side stream.
    cudaEventRecord(ev_fork, 0);
    cudaStreamWaitEvent(s_side, ev_fork, 0);

    // side: pack_bd (feeds delta), cvt_half (feeds main GEMM).
    pack_bd_kernel<<<((size_t)OUT_DIM * KPACK + 255) / 256, 256, 0, s_side>>>(
        Bd, gbdp);
    cudaEventRecord(ev_pack, s_side);
    cvt_half_kernel<<<(33554432 / 4 + 255) / 256, 256, 0, s_side>>>(
        x, gxh, 33554432 / 4);

    // main: pack_bu || side; then delta halves.
    pack_bu_kernel<<<dim3(RANK_ / 32, IN_DIM / 32), dim3(32, 8)>>>(Bu, gbup);
    cudaStreamWaitEvent(0, ev_pack, 0);
    gemm_delta_f16<<<dim3(IN_DIM / BN, NT_HALF), 256, DGEMM_SMEM>>>(
        gbdp, gbup, weight, gw, 0);
    cudaEventRecord(ev_dA, 0);
    gemm_delta_f16<<<dim3(IN_DIM / BN, NT_HALF), 256, DGEMM_SMEM>>>(
        gbdp, gbup, weight, gw, NT_HALF);
    cudaEventRecord(ev_dB, 0);

    // side: quantA overlaps deltaB; quantB overlaps mainA.
    cudaStreamWaitEvent(s_side, ev_dA, 0);
    quant_kernel<<<HROWS, 256, 0, s_side>>>(gw, gwh, 0);
    cudaEventRecord(ev_qA, s_side);
    cudaStreamWaitEvent(s_side, ev_dB, 0);
    quant_kernel<<<HROWS, 256, 0, s_side>>>(gw, gwh, HROWS);

    // main: mainA (needs quantA + xh; ev_qA was recorded after cvt on side).
    cudaStreamWaitEvent(0, ev_qA, 0);
    gemm_main_fp16<<<MTILES * NT_HALF, 256, GEMM_SMEM>>>(
        gxh, gwh, bias, (float*)d_out, 0);

    // side: mainB (after quantB on same stream) — backfills mainA's drain.
    gemm_main_fp16<<<MTILES * NT_HALF, 256, GEMM_SMEM, s_side>>>(
        gxh, gwh, bias, (float*)d_out, NT_HALF);
    cudaEventRecord(ev_end, s_side);

    // Join side back into the origin stream.
    cudaStreamWaitEvent(0, ev_end, 0);
}

// round 17
// speedup vs baseline: 1.0701x; 1.0025x over previous
#include <cuda_runtime.h>
#include <cuda_fp16.h>
#include <cstdint>
#include <cstddef>

// Problem dims (fixed by the dataset)
#define M_DIM   8192      // 4*2048 rows of x
#define IN_DIM  4096      // K of main GEMM
#define OUT_DIM 11008     // N of main GEMM
#define RANK_   192
#define KPACK   576       // 3 * RANK_  (compensated-product K concat)

// ---------------------------------------------------------------------------
// Scratch (static __device__ arrays — allocation-free per harness rules)
// ---------------------------------------------------------------------------
__device__ __align__(256) float  g_w  [(size_t)OUT_DIM * IN_DIM];  // weight+delta fp32
__device__ __align__(256) __half g_xh [(size_t)M_DIM  * IN_DIM];   // x as fp16
__device__ __align__(256) __half g_wh [(size_t)OUT_DIM * IN_DIM];  // quantized w fp16
__device__ __align__(256) __half g_bdp[(size_t)OUT_DIM * KPACK];   // [Ah|Ah|Al] of 64*Bd
__device__ __align__(256) __half g_bup[(size_t)IN_DIM * KPACK];    // [Bh|Bl|Bh] of 64*Bu, [N,K]

// ---------------------------------------------------------------------------
// x -> fp16
// ---------------------------------------------------------------------------
__global__ void cvt_half_kernel(const float* __restrict__ in,
                                __half* __restrict__ out, int n4) {
    int i = blockIdx.x * 256 + threadIdx.x;
    if (i < n4) {
        float4 v = reinterpret_cast<const float4*>(in)[i];
        __half2 h0 = __floats2half2_rn(v.x, v.y);
        __half2 h1 = __floats2half2_rn(v.z, v.w);
        uint2 p;
        p.x = *reinterpret_cast<uint32_t*>(&h0);
        p.y = *reinterpret_cast<uint32_t*>(&h1);
        reinterpret_cast<uint2*>(out)[i] = p;
    }
}

// ---------------------------------------------------------------------------
// Pack kernels: hi/lo fp16 split of 64*Bd / 64*Bu, K-concatenated so that a
// single fp16 GEMM computes Ah*Bh + Ah*Bl + Al*Bh (fp32-accurate product).
// ---------------------------------------------------------------------------
__global__ void pack_bd_kernel(const float* __restrict__ bd,
                               __half* __restrict__ out) {
    size_t i = (size_t)blockIdx.x * 256 + threadIdx.x;
    if (i < (size_t)OUT_DIM * KPACK) {
        int o = (int)(i / KPACK), c = (int)(i % KPACK);
        int r = (c < 192) ? c : ((c < 384) ? c - 192 : c - 384);
        float v = bd[(size_t)o * RANK_ + r] * 64.0f;
        __half h = __float2half_rn(v);
        out[i] = (c < 384) ? h : __float2half_rn(v - __half2float(h));
    }
}

// Tiled-transpose pack for Bu — coalesced reads AND writes.
__global__ void pack_bu_kernel(const float* __restrict__ bu,
                               __half* __restrict__ out) {
    __shared__ float t[32][33];
    const int r0 = blockIdx.x * 32;
    const int n0 = blockIdx.y * 32;
    const int tx = threadIdx.x, ty = threadIdx.y;   // 32 x 8

    #pragma unroll
    for (int j = 0; j < 32; j += 8)
        t[ty + j][tx] = bu[(size_t)(r0 + ty + j) * IN_DIM + n0 + tx];
    __syncthreads();

    #pragma unroll
    for (int j = 0; j < 32; j += 8) {
        const int n = n0 + ty + j;
        float v = t[tx][ty + j] * 64.0f;
        __half h = __float2half_rn(v);
        __half l = __float2half_rn(v - __half2float(h));
        __half* o = out + (size_t)n * KPACK + r0 + tx;
        o[0]   = h;
        o[192] = l;
        o[384] = h;
    }
}

// ---------------------------------------------------------------------------
// Row-wise 4-bit asymmetric fake quant: fp32 g_w (row cached) -> fp16 g_wh.
// rowOff selects the row range being processed.
// ---------------------------------------------------------------------------
__global__ void quant_kernel(const float* __restrict__ w, __half* __restrict__ wh,
                             int rowOff) {
    __shared__ float row[IN_DIM];
    __shared__ float smn[8], smx[8];
    __shared__ float s_scale, s_zero;

    const int rix = blockIdx.x + rowOff;
    const float* p = w + (size_t)rix * IN_DIM;
    __half* po = wh + (size_t)rix * IN_DIM;
    const int tid = threadIdx.x;

    float mn = 0.0f, mx = 0.0f;
    #pragma unroll
    for (int i = tid; i < IN_DIM / 4; i += 256) {
        float4 v = reinterpret_cast<const float4*>(p)[i];
        reinterpret_cast<float4*>(row)[i] = v;
        mn = fminf(mn, fminf(fminf(v.x, v.y), fminf(v.z, v.w)));
        mx = fmaxf(mx, fmaxf(fmaxf(v.x, v.y), fmaxf(v.z, v.w)));
    }
    #pragma unroll
    for (int o = 16; o; o >>= 1) {
        mn = fminf(mn, __shfl_xor_sync(0xffffffffu, mn, o));
        mx = fmaxf(mx, __shfl_xor_sync(0xffffffffu, mx, o));
    }
    const int warp = tid >> 5, lane = tid & 31;
    if (lane == 0) { smn[warp] = mn; smx[warp] = mx; }
    __syncthreads();
    if (tid == 0) {
        float a = smn[0], b = smx[0];
        #pragma unroll
        for (int i = 1; i < 8; i++) { a = fminf(a, smn[i]); b = fmaxf(b, smx[i]); }
        float sc = fmaxf((b - a) / 15.0f, 1e-8f);
        s_scale = sc;
        s_zero  = rintf(-a / sc);
    }
    __syncthreads();
    const float sc = s_scale, z = s_zero;

    #pragma unroll
    for (int i = tid; i < IN_DIM / 4; i += 256) {
        float4 v = reinterpret_cast<float4*>(row)[i];
        float q0 = (fminf(fmaxf(rintf(v.x / sc) + z, 0.0f), 15.0f) - z) * sc;
        float q1 = (fminf(fmaxf(rintf(v.y / sc) + z, 0.0f), 15.0f) - z) * sc;
        float q2 = (fminf(fmaxf(rintf(v.z / sc) + z, 0.0f), 15.0f) - z) * sc;
        float q3 = (fminf(fmaxf(rintf(v.w / sc) + z, 0.0f), 15.0f) - z) * sc;
        __half2 h0 = __floats2half2_rn(q0, q1);
        __half2 h1 = __floats2half2_rn(q2, q3);
        uint2 pk;
        pk.x = *reinterpret_cast<uint32_t*>(&h0);
        pk.y = *reinterpret_cast<uint32_t*>(&h1);
        reinterpret_cast<uint2*>(po)[i] = pk;
    }
}

// ---------------------------------------------------------------------------
// Shared GEMM building blocks
// ---------------------------------------------------------------------------
__device__ __forceinline__ void cp16(uint32_t s, const void* g) {
    asm volatile("cp.async.cg.shared.global [%0], [%1], 16;\n" :: "r"(s), "l"(g));
}
__device__ __forceinline__ void ldsm_x4(uint32_t* r, uint32_t addr) {
    asm volatile("ldmatrix.sync.aligned.m8n8.x4.shared.b16 {%0,%1,%2,%3}, [%4];"
                 : "=r"(r[0]), "=r"(r[1]), "=r"(r[2]), "=r"(r[3]) : "r"(addr));
}
__device__ __forceinline__ void mma_f16(float* d, const uint32_t* a,
                                        uint32_t b0, uint32_t b1) {
    asm volatile(
        "mma.sync.aligned.m16n8k16.row.col.f32.f16.f16.f32 "
        "{%0,%1,%2,%3}, {%4,%5,%6,%7}, {%8,%9}, {%0,%1,%2,%3};\n"
        : "+f"(d[0]), "+f"(d[1]), "+f"(d[2]), "+f"(d[3])
        : "r"(a[0]), "r"(a[1]), "r"(a[2]), "r"(a[3]), "r"(b0), "r"(b1));
}

// Main GEMM geometry (R9/R11/R14 optimum): CTA 128x128, 256 thr, 2 CTA/SM,
// K-chunk 64 halves, ROWB=144, 3-stage cp.async.
#define BM 128
#define BN 128
#define BKH 64
#define ROWB 144
#define A_BYTES (BM * ROWB)               // 18432
#define B_BYTES (BN * ROWB)               // 18432
#define STAGE_BYTES (A_BYTES + B_BYTES)   // 36864
#define NSTAGE 3
#define GEMM_SMEM (NSTAGE * STAGE_BYTES)  // 110592
#define KTILES_MAIN (IN_DIM / BKH)        // 64
#define MTILES (M_DIM / BM)               // 64
#define EPI_STRIDE 136

// Delta GEMM geometry: 128x128 / 256 thr / 2 CTA/SM, BKH=32, 5-stage.
#define DBKH 32
#define DROWB 80
#define DA_BYTES (BM * DROWB)             // 10240
#define DB_BYTES (BN * DROWB)             // 10240
#define DSTAGE_BYTES (DA_BYTES + DB_BYTES)  // 20480
#define DNSTAGE 5
#define DGEMM_SMEM (DNSTAGE * DSTAGE_BYTES) // 102400
#define KTILES_DELTA (KPACK / DBKH)       // 18

// ---------------------------------------------------------------------------
// Delta GEMM (fp16, K=576): g_w[11008, 4096] = weight + (bdp @ bup^T)/4096
// Single full launch (grid 32 x 86).
// ---------------------------------------------------------------------------
__global__ __launch_bounds__(256, 2)
void gemm_delta_f16(const __half* __restrict__ ap, const __half* __restrict__ bp,
                    const float* __restrict__ wgt, float* __restrict__ outw) {
    extern __shared__ __align__(128) unsigned char smem[];
    const uint32_t sb = (uint32_t)__cvta_generic_to_shared(smem);
    const int tid = threadIdx.x, warp = tid >> 5, lane = tid & 31;
    const int wm = warp & 1, wn = warp >> 1;

    const int mBase = blockIdx.y * BM, nBase = blockIdx.x * BN;

    const __half* gA[2]; uint32_t sAoff[2];
    const __half* gB[2]; uint32_t sBoff[2];
    #pragma unroll
    for (int i = 0; i < 2; i++) {
        int c = tid + i * 256;
        int r = c >> 2, s = c & 3;
        gA[i] = ap + (size_t)(mBase + r) * KPACK + s * 8;
        sAoff[i] = r * DROWB + s * 16;
        gB[i] = bp + (size_t)(nBase + r) * KPACK + s * 8;
        sBoff[i] = DA_BYTES + r * DROWB + s * 16;
    }

    auto issue = [&](int kt) {
        const uint32_t base = sb + (uint32_t)(kt % DNSTAGE) * DSTAGE_BYTES;
        const int koff = kt * DBKH;
        #pragma unroll
        for (int i = 0; i < 2; i++) cp16(base + sAoff[i], gA[i] + koff);
        #pragma unroll
        for (int i = 0; i < 2; i++) cp16(base + sBoff[i], gB[i] + koff);
        asm volatile("cp.async.commit_group;\n");
    };

    const int mat = lane >> 3, mrow = lane & 7;
    const uint32_t aAddr0 = (uint32_t)(wm * 64 + ((mat & 1) << 3) + mrow) * DROWB
                          + ((mat >> 1) << 4);
    const uint32_t bAddr0 = DA_BYTES
                          + (uint32_t)(wn * 32 + ((mat >> 1) << 3) + mrow) * DROWB
                          + ((mat & 1) << 4);

    float acc[4][4][4];
    #pragma unroll
    for (int i = 0; i < 4; i++)
        #pragma unroll
        for (int j = 0; j < 4; j++)
            #pragma unroll
            for (int k = 0; k < 4; k++) acc[i][j][k] = 0.0f;

    issue(0); issue(1); issue(2); issue(3);

    for (int kt = 0; kt < KTILES_DELTA; ++kt) {
        const int rem = KTILES_DELTA - 1 - kt;
        if (rem >= 3)      { asm volatile("cp.async.wait_group 3;\n"); }
        else if (rem == 2) { asm volatile("cp.async.wait_group 2;\n"); }
        else if (rem == 1) { asm volatile("cp.async.wait_group 1;\n"); }
        else               { asm volatile("cp.async.wait_group 0;\n"); }
        __syncthreads();
        if (kt + 4 < KTILES_DELTA) issue(kt + 4);

        const uint32_t base = sb + (uint32_t)(kt % DNSTAGE) * DSTAGE_BYTES;

        #pragma unroll
        for (int kk = 0; kk < 2; ++kk) {
            uint32_t af[4][4], bf[2][4];
            #pragma unroll
            for (int mi = 0; mi < 4; ++mi)
                ldsm_x4(af[mi], base + aAddr0 + mi * (16 * DROWB) + kk * 32);
            #pragma unroll
            for (int nj = 0; nj < 2; ++nj)
                ldsm_x4(bf[nj], base + bAddr0 + nj * (16 * DROWB) + kk * 32);
            #pragma unroll
            for (int mi = 0; mi < 4; ++mi) {
                #pragma unroll
                for (int nj = 0; nj < 2; ++nj) {
                    mma_f16(acc[mi][nj * 2],     af[mi], bf[nj][0], bf[nj][1]);
                    mma_f16(acc[mi][nj * 2 + 1], af[mi], bf[nj][2], bf[nj][3]);
                }
            }
        }
    }

    // Epilogue via smem staging, then coalesced float4 stream.
    __syncthreads();
    float* st = reinterpret_cast<float*>(smem);
    {
        const int mr = wm * 64 + (lane >> 2);
        const int nc = wn * 32 + ((lane & 3) << 1);
        #pragma unroll
        for (int mi = 0; mi < 4; ++mi) {
            const int m0 = mr + mi * 16;
            #pragma unroll
            for (int njh = 0; njh < 4; ++njh) {
                const int n = nc + njh * 8;
                st[m0 * EPI_STRIDE + n]           = acc[mi][njh][0];
                st[m0 * EPI_STRIDE + n + 1]       = acc[mi][njh][1];
                st[(m0 + 8) * EPI_STRIDE + n]     = acc[mi][njh][2];
                st[(m0 + 8) * EPI_STRIDE + n + 1] = acc[mi][njh][3];
            }
        }
    }
    __syncthreads();
    const float SC = 1.0f / 4096.0f;
    #pragma unroll
    for (int it = 0; it < 16; ++it) {
        int i = tid + it * 256;
        int row = i >> 5, c4 = i & 31;
        float4 v = *reinterpret_cast<float4*>(&st[row * EPI_STRIDE + c4 * 4]);
        size_t gofs = (size_t)(mBase + row) * IN_DIM + nBase + c4 * 4;
        float4 w4 = *reinterpret_cast<const float4*>(&wgt[gofs]);
        v.x = v.x * SC + w4.x;
        v.y = v.y * SC + w4.y;
        v.z = v.z * SC + w4.z;
        v.w = v.w * SC + w4.w;
        *reinterpret_cast<float4*>(&outw[gofs]) = v;
    }
}

// ---------------------------------------------------------------------------
// Main GEMM slice: out[:, (nTileOff..nTileOff+NT)*128) = xh @ wh^T + bias
// nsc = number of full 8-wide n-supercolumns; remw = remainder width (0 ok if
// grid exactly covers the full supercolumns).
// ---------------------------------------------------------------------------
__global__ __launch_bounds__(256, 2)
void gemm_main_fp16(const __half* __restrict__ xh, const __half* __restrict__ wh,
                    const float* __restrict__ bias, float* __restrict__ out,
                    int nTileOff, int nsc, int remw) {
    extern __shared__ __align__(128) unsigned char smem[];
    const uint32_t sb = (uint32_t)__cvta_generic_to_shared(smem);
    const int tid = threadIdx.x, warp = tid >> 5, lane = tid & 31;
    const int wm = warp & 1, wn = warp >> 1;   // 2M x 4N warps, warp tile 64x32

    int g = blockIdx.x, mTile, nT;
    const int fullCnt = MTILES * 8 * nsc;
    if (g < fullCnt) {
        int sc = g >> 9, loc = g & 511;
        nT = sc * 8 + (loc & 7);
        mTile = loc >> 3;
    } else {
        int loc = g - fullCnt;
        nT = nsc * 8 + loc % remw;
        mTile = loc / remw;
    }
    const int mBase = mTile * BM, nBase = (nTileOff + nT) * BN;

    const __half* gA[4]; uint32_t sAoff[4];
    const __half* gB[4]; uint32_t sBoff[4];
    #pragma unroll
    for (int i = 0; i < 4; i++) {
        int c = tid + i * 256;
        int r = c >> 3, s = c & 7;
        gA[i] = xh + (size_t)(mBase + r) * IN_DIM + s * 8;
        sAoff[i] = r * ROWB + s * 16;
        gB[i] = wh + (size_t)(nBase + r) * IN_DIM + s * 8;
        sBoff[i] = A_BYTES + r * ROWB + s * 16;
    }

    auto issue = [&](int kt) {
        const uint32_t base = sb + (uint32_t)(kt % NSTAGE) * STAGE_BYTES;
        const int koff = kt * BKH;
        #pragma unroll
        for (int i = 0; i < 4; i++) cp16(base + sAoff[i], gA[i] + koff);
        #pragma unroll
        for (int i = 0; i < 4; i++) cp16(base + sBoff[i], gB[i] + koff);
        asm volatile("cp.async.commit_group;\n");
    };

    const int mat = lane >> 3, mrow = lane & 7;
    const uint32_t aAddr0 = (uint32_t)(wm * 64 + ((mat & 1) << 3) + mrow) * ROWB
                          + ((mat >> 1) << 4);
    const uint32_t bAddr0 = A_BYTES
                          + (uint32_t)(wn * 32 + ((mat >> 1) << 3) + mrow) * ROWB
                          + ((mat & 1) << 4);

    float acc[4][4][4];
    #pragma unroll
    for (int i = 0; i < 4; i++)
        #pragma unroll
        for (int j = 0; j < 4; j++)
            #pragma unroll
            for (int k = 0; k < 4; k++) acc[i][j][k] = 0.0f;

    issue(0); issue(1);

    for (int kt = 0; kt < KTILES_MAIN; ++kt) {
        if (kt < KTILES_MAIN - 1) { asm volatile("cp.async.wait_group 1;\n"); }
        else                      { asm volatile("cp.async.wait_group 0;\n"); }
        __syncthreads();
        if (kt + 2 < KTILES_MAIN) issue(kt + 2);

        const uint32_t base = sb + (uint32_t)(kt % NSTAGE) * STAGE_BYTES;

        #pragma unroll
        for (int kk = 0; kk < 4; ++kk) {
            uint32_t af[4][4], bf[2][4];
            #pragma unroll
            for (int mi = 0; mi < 4; ++mi)
                ldsm_x4(af[mi], base + aAddr0 + mi * (16 * ROWB) + kk * 32);
            #pragma unroll
            for (int nj = 0; nj < 2; ++nj)
                ldsm_x4(bf[nj], base + bAddr0 + nj * (16 * ROWB) + kk * 32);
            #pragma unroll
            for (int mi = 0; mi < 4; ++mi) {
                #pragma unroll
                for (int nj = 0; nj < 2; ++nj) {
                    mma_f16(acc[mi][nj * 2],     af[mi], bf[nj][0], bf[nj][1]);
                    mma_f16(acc[mi][nj * 2 + 1], af[mi], bf[nj][2], bf[nj][3]);
                }
            }
        }
    }

    const int mRow = mBase + wm * 64 + (lane >> 2);
    const int nCol = nBase + wn * 32 + ((lane & 3) << 1);
    #pragma unroll
    for (int mi = 0; mi < 4; ++mi) {
        const int m0 = mRow + mi * 16;
        #pragma unroll
        for (int njh = 0; njh < 4; ++njh) {
            const int n = nCol + njh * 8;
            float2 b2 = *reinterpret_cast<const float2*>(&bias[n]);
            float2 o0 = make_float2(acc[mi][njh][0] + b2.x, acc[mi][njh][1] + b2.y);
            float2 o1 = make_float2(acc[mi][njh][2] + b2.x, acc[mi][njh][3] + b2.y);
            *reinterpret_cast<float2*>(&out[(size_t)m0 * OUT_DIM + n])       = o0;
            *reinterpret_cast<float2*>(&out[(size_t)(m0 + 8) * OUT_DIM + n]) = o1;
        }
    }
}

// ---------------------------------------------------------------------------
// Launch — event-exact overlap DAG:
//   side:  pack_bd -> ev_pack -> cvt_half -> ev_cvt
//          -> wait(ev_delta) quantRest(rows 1024..11007)
//          -> mainRest (nTiles 8..85)  -> ev_end
//   main:  pack_bu -> wait(ev_pack) -> delta(full) -> ev_delta
//          -> quant1(rows 0..1023) -> wait(ev_cvt) -> mainA (nTiles 0..7)
//          -> wait(ev_end)
// quantRest hides under mainA; mainRest backfills mainA's tail.
// ---------------------------------------------------------------------------
extern "C" void kernel_launch(void* const* d_in, const int* in_sizes, int n_in,
                              void* d_out, int out_size) {
    const float *x = nullptr, *weight = nullptr, *Bd = nullptr,
                *Bu = nullptr, *bias = nullptr;
    for (int i = 0; i < n_in; i++) {
        switch (in_sizes[i]) {
            case 33554432: x      = (const float*)d_in[i]; break;  // 8192*4096
            case 45088768: weight = (const float*)d_in[i]; break;  // 11008*4096
            case 2113536:  Bd     = (const float*)d_in[i]; break;  // 11008*192
            case 786432:   Bu     = (const float*)d_in[i]; break;  // 192*4096
            case 11008:    bias   = (const float*)d_in[i]; break;
        }
    }
    if (!x && n_in > 0)      x      = (const float*)d_in[0];
    if (!weight && n_in > 1) weight = (const float*)d_in[1];
    if (!Bd && n_in > 2)     Bd     = (const float*)d_in[2];
    if (!Bu && n_in > 3)     Bu     = (const float*)d_in[3];
    if (!bias && n_in > 4)   bias   = (const float*)d_in[4];

    float *gw;
    __half *gxh, *gwh, *gbdp, *gbup;
    cudaGetSymbolAddress((void**)&gw,   g_w);
    cudaGetSymbolAddress((void**)&gxh,  g_xh);
    cudaGetSymbolAddress((void**)&gwh,  g_wh);
    cudaGetSymbolAddress((void**)&gbdp, g_bdp);
    cudaGetSymbolAddress((void**)&gbup, g_bup);

    cudaFuncSetAttribute(gemm_delta_f16,
                         cudaFuncAttributeMaxDynamicSharedMemorySize, DGEMM_SMEM);
    cudaFuncSetAttribute(gemm_main_fp16,
                         cudaFuncAttributeMaxDynamicSharedMemorySize, GEMM_SMEM);

    // One-time host resources (no device memory involved).
    static cudaStream_t s_side = nullptr;
    static cudaEvent_t ev_fork = nullptr, ev_pack = nullptr, ev_cvt = nullptr,
                       ev_delta = nullptr, ev_end = nullptr;
    if (s_side == nullptr) {
        cudaStreamCreateWithFlags(&s_side, cudaStreamNonBlocking);
        cudaEventCreateWithFlags(&ev_fork,  cudaEventDisableTiming);
        cudaEventCreateWithFlags(&ev_pack,  cudaEventDisableTiming);
        cudaEventCreateWithFlags(&ev_cvt,   cudaEventDisableTiming);
        cudaEventCreateWithFlags(&ev_delta, cudaEventDisableTiming);
        cudaEventCreateWithFlags(&ev_end,   cudaEventDisableTiming);
    }

    // Fork side stream.
    cudaEventRecord(ev_fork, 0);
    cudaStreamWaitEvent(s_side, ev_fork, 0);

    // side: pack_bd (feeds delta), then cvt_half (feeds both main slices).
    pack_bd_kernel<<<((size_t)OUT_DIM * KPACK + 255) / 256, 256, 0, s_side>>>(
        Bd, gbdp);
    cudaEventRecord(ev_pack, s_side);
    cvt_half_kernel<<<(33554432 / 4 + 255) / 256, 256, 0, s_side>>>(
        x, gxh, 33554432 / 4);
    cudaEventRecord(ev_cvt, s_side);

    // main: pack_bu || side; then full delta.
    pack_bu_kernel<<<dim3(RANK_ / 32, IN_DIM / 32), dim3(32, 8)>>>(Bu, gbup);
    cudaStreamWaitEvent(0, ev_pack, 0);
    gemm_delta_f16<<<dim3(IN_DIM / BN, OUT_DIM / BM), 256, DGEMM_SMEM>>>(
        gbdp, gbup, weight, gw);
    cudaEventRecord(ev_delta, 0);

    // main: quant rows [0,1024) — the only quant on the critical path.
    quant_kernel<<<1024, 256>>>(gw, gwh, 0);

    // main: mainA = n-supercolumn 0 (nTiles 0..7, 512 CTAs). Needs cvt + quant1.
    cudaStreamWaitEvent(0, ev_cvt, 0);
    gemm_main_fp16<<<MTILES * 8, 256, GEMM_SMEM>>>(
        gxh, gwh, bias, (float*)d_out, 0, 1, 0);

    // side: quantRest (rows 1024..11007) hides under mainA; then mainRest
    // (nTiles 8..85 = 9 full supercolumns + remainder 6) backfills mainA.
    cudaStreamWaitEvent(s_side, ev_delta, 0);
    quant_kernel<<<OUT_DIM - 1024, 256, 0, s_side>>>(gw, gwh, 1024);
    gemm_main_fp16<<<MTILES * 78, 256, GEMM_SMEM, s_side>>>(
        gxh, gwh, bias, (float*)d_out, 8, 9, 6);
    cudaEventRecord(ev_end, s_side);

    // Join side back into the origin stream.
    cudaStreamWaitEvent(0, ev_end, 0);
}